// round 14
// baseline (speedup 1.0000x reference)
#include <cuda_runtime.h>

#define NINST 100
#define HW 819200              // 640*1280
#define TPB 256
#define PXT 4                  // pixels per thread (float4)
#define NTILES 800             // reader tiles: 256*4*800 = HW
#define GRID 592               // 148 SMs x 4 resident = single persistent wave
#define UCH 4                  // planes per pipeline chunk (double-buffered)

// ---------------- static device state (no allocations) ----------------
__device__ unsigned g_tile;                            // work-stealing cursor
__device__ unsigned g_rawcnt;                          // epilogue resets these
__device__ unsigned g_npairs;
__device__ unsigned g_done;
__device__ __align__(16) unsigned long long g_rec[HW]; // packed (p | nA<<20 | nB<<27)
__device__ __align__(16) unsigned g_pair[HW];          // packed (nA | nB<<8)

#define LOADC(buf, c0)                                                         \
    _Pragma("unroll")                                                          \
    for (int u = 0; u < UCH; u++)                                              \
        buf[u] = __ldcs(reinterpret_cast<const float4*>(                       \
            mask + (size_t)sord[(c0) + u] * HW + p0));

#define CONSUME(buf)                                                           \
    _Pragma("unroll")                                                          \
    for (int u = 0; u < UCH; u++) {                                            \
        float vv[PXT] = { buf[u].x, buf[u].y, buf[u].z, buf[u].w };            \
        _Pragma("unroll")                                                      \
        for (int e = 0; e < PXT; e++) {                                        \
            m1[e] = fmaxf(m1[e], vv[e]);                                       \
            s[e] += __expf(vv[e]);                                             \
        }                                                                      \
    }

// ---------------- pure-read persistent kernel, double-buffered ----------------
// Output pre-zeroed by cudaMemsetAsync (pure-write phase at full rate). This
// kernel is a PURE READ stream: per-pixel running max + unshifted sum(exp)
// over the 100 planes in descending-confidence order; rare candidate emission
// (softmax >= 0.4 admits at most the per-pixel top-2). Ping-pong buffers keep
// UCH LDG.128 outstanding per warp at ALL times (R13 showed the single-buffer
// version idles DRAM during consume phases -> 58.6% duty cycle).
// Phase 2 (last-finishing block): greedy merge on the compact record list.
__global__ void __launch_bounds__(TPB, 4) k_read(const float* __restrict__ mask,
                                                 float* __restrict__ masks_out,
                                                 const float* __restrict__ cls_prob,
                                                 const int*   __restrict__ cls_idx,
                                                 float* keep_out, float* order_out) {
    __shared__ float v[NINST];
    __shared__ int sord[NINST];
    __shared__ int sci[NINST];
    __shared__ int hist[NINST];
    __shared__ int skeep[NINST];
    __shared__ unsigned affected[4];
    __shared__ unsigned stile;
    __shared__ int slast;

    int t = threadIdx.x;

    // ---- block-local argsort: stable ascending rank, reversed ----
    if (t < NINST) v[t] = cls_prob[t];
    __syncthreads();
    if (t < NINST) {
        float x = v[t];
        int r = 0;
#pragma unroll 4
        for (int j = 0; j < NINST; j++)
            r += (v[j] < x) || (v[j] == x && j < t);
        sord[NINST - 1 - r] = t;
    }
    __syncthreads();
    if (blockIdx.x == 0 && t < NINST && order_out) order_out[t] = (float)sord[t];

    // ---- persistent work-stealing over pure-read tiles ----
    for (;;) {
        if (t == 0) stile = atomicAdd(&g_tile, 1u);
        __syncthreads();
        unsigned tile = stile;
        __syncthreads();                       // stile reusable next iter
        if (tile >= NTILES) break;

        int p0 = (int)tile * (TPB * PXT) + t * PXT;

        float m1[PXT], s[PXT];
#pragma unroll
        for (int e = 0; e < PXT; e++) { m1[e] = __int_as_float(0xff800000); s[e] = 0.f; }

        // ping-pong pipeline over 25 chunks of 4 planes (order 0..99 preserved)
        float4 A[UCH], B[UCH];
        LOADC(A, 0);
#pragma unroll 2
        for (int c = 0; c < 12; c++) {
            LOADC(B, (2 * c + 1) * UCH);
            CONSUME(A);
            LOADC(A, (2 * c + 2) * UCH);
            CONSUME(B);
        }
        CONSUME(A);                            // chunk 24 (planes 96..99)

        // ---- rare candidate emission (second pass recovers top-2 ranks) ----
#pragma unroll
        for (int e = 0; e < PXT; e++) {
            float thr = 0.4f * s[e];
            if (__expf(m1[e]) >= thr) {
                const float* col = mask + p0 + e;
                float b1 = __int_as_float(0xff800000), b2 = b1;
                int j1 = 127, j2 = 127;
                for (int n = 0; n < NINST; n++) {
                    float val = __ldg(col + (size_t)sord[n] * HW);
                    bool g1 = val > b1;
                    bool g2 = val > b2;
                    j2 = g1 ? j1 : (g2 ? n : j2);
                    b2 = g1 ? b1 : (g2 ? val : b2);
                    j1 = g1 ? n : j1;
                    b1 = g1 ? val : b1;
                }
                bool c2 = (j2 < NINST) && (__expf(b2) >= thr);
                int a = j1, b = c2 ? j2 : 127;
                if (c2 && b < a) { int tmp = a; a = b; b = tmp; }   // nA earlier
                unsigned pos = atomicAdd(&g_rawcnt, 1u);
                g_rec[pos] = (unsigned long long)(unsigned)(p0 + e)
                           | ((unsigned long long)a << 20)
                           | ((unsigned long long)b << 27);
            }
        }
    }

    // ---- last-block-done handoff ----
    __syncthreads();
    __threadfence();                       // publish g_rec
    if (t == 0) {
        unsigned old = atomicAdd(&g_done, 1u);
        slast = (old == (unsigned)(gridDim.x - 1)) ? 1 : 0;
    }
    __syncthreads();
    if (!slast) return;
    __threadfence();                       // acquire other blocks' records

    // ---- phase 2: greedy merge (one block) ----
    // overlap(n) > 0 requires a same-class pair at the same pixel (doubly rare):
    //   hist[n] = binarized mask_sum; default keep = 0 < hist < HW, exact unless
    //   n is the later partner nB of a same-class pair -> sequential fixup.
    //   assign(nA) iff keep[nA]; assign(nB) iff keep[nB] && !keep[nA]
    if (t < NINST) { sci[t] = cls_idx[sord[t]]; hist[t] = 0; }
    if (t < 4) affected[t] = 0;
    __syncthreads();

    unsigned cnt = g_rawcnt; if (cnt > HW) cnt = HW;
    for (unsigned i = t; i < cnt; i += TPB) {
        unsigned long long r = g_rec[i];
        int nA = (int)(r >> 20) & 0x7F;
        int nB = (int)(r >> 27) & 0x7F;
        atomicAdd(&hist[nA], 1);
        if (nB < NINST) {
            atomicAdd(&hist[nB], 1);
            if (sci[nA] == sci[nB]) {
                unsigned pos = atomicAdd(&g_npairs, 1u);
                g_pair[pos] = (unsigned)nA | ((unsigned)nB << 8);
                atomicOr(&affected[nB >> 5], 1u << (nB & 31));
            }
        }
    }
    __syncthreads();

    unsigned np = g_npairs; if (np > HW) np = HW;
    if (t < NINST) skeep[t] = (hist[t] > 0 && hist[t] < HW) ? 1 : 0;
    __syncthreads();

    if (t < 32 && (affected[0] | affected[1] | affected[2] | affected[3])) {
        for (int n = 0; n < NINST; n++) {
            if (!((affected[n >> 5] >> (n & 31)) & 1u)) continue;
            if (!skeep[n]) continue;
            int ov = 0;
            for (unsigned i = t; i < np; i += 32) {
                unsigned pr = g_pair[i];
                if ((int)(pr >> 8) == n) ov += skeep[pr & 0xFFu];
            }
            ov = (int)__reduce_add_sync(0xffffffffu, (unsigned)ov);
            if (t == 0 && ((float)ov / fmaxf((float)hist[n], 1.0f)) > 0.03f)
                skeep[n] = 0;
            __syncwarp();
        }
    }
    __syncthreads();

    if (t < NINST && keep_out) keep_out[t] = skeep[t] ? 1.0f : 0.0f;

    for (unsigned i = t; i < cnt; i += TPB) {
        unsigned long long r = g_rec[i];
        unsigned p = (unsigned)(r & 0xFFFFFu);
        int nA = (int)(r >> 20) & 0x7F;
        int nB = (int)(r >> 27) & 0x7F;
        if (skeep[nA])
            masks_out[(size_t)nA * HW + p] = mask[(size_t)sord[nA] * HW + p];
        if (nB < NINST && skeep[nB] && !skeep[nA])
            masks_out[(size_t)nB * HW + p] = mask[(size_t)sord[nB] * HW + p];
    }

    __syncthreads();
    if (t == 0) { g_rawcnt = 0; g_npairs = 0; g_done = 0; g_tile = 0; } // replay reset
}

// ---------------- launch: pure-write memset, then pure-read kernel ----------------
extern "C" void kernel_launch(void* const* d_in, const int* in_sizes, int n_in,
                              void* d_out, int out_size) {
    const float* cls_prob = (const float*)d_in[0];
    const float* mask     = (const float*)d_in[1];
    const int*   cls_idx  = (const int*)d_in[2];
    float* out = (float*)d_out;

    size_t nhw = (size_t)NINST * HW;
    float* keep_out  = out;
    float* masks_out = out + NINST;
    float* order_out = out + NINST + nhw;
    if ((size_t)out_size < nhw + 2 * NINST) {   // layout fallback: masks only
        keep_out = nullptr; order_out = nullptr; masks_out = out;
    }

    cudaMemsetAsync(d_out, 0, (size_t)out_size * sizeof(float), 0);
    k_read<<<GRID, TPB>>>(mask, masks_out, cls_prob, cls_idx,
                          keep_out, order_out);
}

// round 16
// speedup vs baseline: 1.1447x; 1.1447x over previous
#include <cuda_runtime.h>

#define NINST 100
#define HW 819200              // 640*1280
#define TPB 256
#define PXT 4                  // pixels per thread (float4 = 16B per plane)
#define NTILES 800             // reader tiles: 256*4*800 = HW
#define GRID 444               // 148 SMs x 3 resident (smem-limited) single wave
#define CH 8                   // planes per cp.async chunk
#define CHB (CH * TPB * 16)    // 32768 B per chunk buffer
#define SMEM_DYN (2 * CHB)     // double buffer: 64 KB

// ---------------- static device state (no allocations) ----------------
__device__ unsigned g_tile;                            // work-stealing cursor
__device__ unsigned g_rawcnt;                          // epilogue resets these
__device__ unsigned g_npairs;
__device__ unsigned g_done;
__device__ __align__(16) unsigned long long g_rec[HW]; // packed (p | nA<<20 | nB<<27)
__device__ __align__(16) unsigned g_pair[HW];          // packed (nA | nB<<8)

// cp.async one chunk of `np` planes into buffer `bsel`; one commit group.
#define CPLOAD(bsel, c0, np)                                                   \
    do {                                                                       \
        _Pragma("unroll")                                                      \
        for (int u = 0; u < (np); u++) {                                       \
            unsigned sa = sbase + (unsigned)((bsel) * CHB + u * (TPB * 16));   \
            const float* srcp = mask + (size_t)sord[(c0) + u] * HW + p0;       \
            asm volatile("cp.async.cg.shared.global [%0], [%1], 16;"           \
                         :: "r"(sa), "l"(srcp));                               \
        }                                                                      \
        asm volatile("cp.async.commit_group;");                                \
    } while (0)

// consume `np` planes from buffer `bsel` (thread reads ONLY its own slots)
#define SCONSUME(bsel, np)                                                     \
    do {                                                                       \
        _Pragma("unroll")                                                      \
        for (int u = 0; u < (np); u++) {                                       \
            float4 val = *reinterpret_cast<const float4*>(                     \
                sdyn + (bsel) * CHB + u * (TPB * 16));                         \
            float vv[PXT] = { val.x, val.y, val.z, val.w };                    \
            _Pragma("unroll")                                                  \
            for (int e = 0; e < PXT; e++) {                                    \
                m1[e] = fmaxf(m1[e], vv[e]);                                   \
                s[e] += __expf(vv[e]);                                         \
            }                                                                  \
        }                                                                      \
    } while (0)

// ---------------- pure-read persistent kernel, cp.async smem pipeline --------
// Output pre-zeroed by cudaMemsetAsync (pure-write phase at full rate). Reads
// stream through a double-buffered cp.async smem pipeline: one 32KB chunk per
// block ALWAYS outstanding (wait_group 1) -> ~96KB/SM in flight, >> BDP, with
// registers staying low (R14 showed register pipelining kills occupancy).
// Chunk c lives in buffer (c & 1); 13 chunks total, so the final 4-plane
// chunk 12 lives in buffer 0 (the R15 bug consumed buffer 1 here).
// Per pixel: running max + unshifted sum(exp) over the 100 planes in
// descending-confidence order; softmax>=0.4 admits at most the per-pixel
// top-2 -> rare divergent second pass recovers ranks.
// Phase 2 (last-finishing block): greedy merge on the compact record list.
__global__ void __launch_bounds__(TPB) k_read(const float* __restrict__ mask,
                                              float* __restrict__ masks_out,
                                              const float* __restrict__ cls_prob,
                                              const int*   __restrict__ cls_idx,
                                              float* keep_out, float* order_out) {
    extern __shared__ char sdyn_raw[];
    char* sdyn = sdyn_raw;                 // [2][CH][TPB] float4
    __shared__ float v[NINST];
    __shared__ int sord[NINST];
    __shared__ int sci[NINST];
    __shared__ int hist[NINST];
    __shared__ int skeep[NINST];
    __shared__ unsigned affected[4];
    __shared__ unsigned stile;
    __shared__ int slast;

    int t = threadIdx.x;

    // ---- block-local argsort: stable ascending rank, reversed ----
    if (t < NINST) v[t] = cls_prob[t];
    __syncthreads();
    if (t < NINST) {
        float x = v[t];
        int r = 0;
#pragma unroll 4
        for (int j = 0; j < NINST; j++)
            r += (v[j] < x) || (v[j] == x && j < t);
        sord[NINST - 1 - r] = t;
    }
    __syncthreads();
    if (blockIdx.x == 0 && t < NINST && order_out) order_out[t] = (float)sord[t];

    unsigned sbase = (unsigned)__cvta_generic_to_shared(sdyn) + (unsigned)(t * 16);
    sdyn += (size_t)t * 16;                // this thread's slot base (generic)

    // ---- persistent work-stealing over pure-read tiles ----
    for (;;) {
        if (t == 0) stile = atomicAdd(&g_tile, 1u);
        __syncthreads();
        unsigned tile = stile;
        __syncthreads();                   // stile reusable next iter
        if (tile >= NTILES) break;

        int p0 = (int)tile * (TPB * PXT) + t * PXT;

        float m1[PXT], s[PXT];
#pragma unroll
        for (int e = 0; e < PXT; e++) { m1[e] = __int_as_float(0xff800000); s[e] = 0.f; }

        // 13 chunks: 12 x 8 planes + 1 x 4 planes. No __syncthreads needed:
        // each thread waits on and reads only its own cp.async data.
        CPLOAD(0, 0, CH);
        for (int c = 0; c < 12; c++) {
            int nb = (c + 1) & 1;
            if (c < 11) CPLOAD(nb, (c + 1) * CH, CH);
            else        CPLOAD(nb, 96, 4);            // chunk 12 -> buffer 0
            asm volatile("cp.async.wait_group 1;" ::: "memory");
            SCONSUME(c & 1, CH);
        }
        asm volatile("cp.async.wait_group 0;" ::: "memory");
        SCONSUME(0, 4);                    // planes 96..99 live in buffer 0

        // ---- rare candidate emission (second pass recovers top-2 ranks) ----
#pragma unroll
        for (int e = 0; e < PXT; e++) {
            float thr = 0.4f * s[e];
            if (__expf(m1[e]) >= thr) {
                const float* col = mask + p0 + e;
                float b1 = __int_as_float(0xff800000), b2 = b1;
                int j1 = 127, j2 = 127;
                for (int n = 0; n < NINST; n++) {
                    float val = __ldg(col + (size_t)sord[n] * HW);
                    bool g1 = val > b1;
                    bool g2 = val > b2;
                    j2 = g1 ? j1 : (g2 ? n : j2);
                    b2 = g1 ? b1 : (g2 ? val : b2);
                    j1 = g1 ? n : j1;
                    b1 = g1 ? val : b1;
                }
                bool c2 = (j2 < NINST) && (__expf(b2) >= thr);
                int a = j1, b = c2 ? j2 : 127;
                if (c2 && b < a) { int tmp = a; a = b; b = tmp; }   // nA earlier
                unsigned pos = atomicAdd(&g_rawcnt, 1u);
                g_rec[pos] = (unsigned long long)(unsigned)(p0 + e)
                           | ((unsigned long long)a << 20)
                           | ((unsigned long long)b << 27);
            }
        }
    }

    // ---- last-block-done handoff ----
    __syncthreads();
    __threadfence();                       // publish g_rec
    if (t == 0) {
        unsigned old = atomicAdd(&g_done, 1u);
        slast = (old == (unsigned)(gridDim.x - 1)) ? 1 : 0;
    }
    __syncthreads();
    if (!slast) return;
    __threadfence();                       // acquire other blocks' records

    // ---- phase 2: greedy merge (one block) ----
    // overlap(n) > 0 requires a same-class pair at the same pixel (doubly rare):
    //   hist[n] = binarized mask_sum; default keep = 0 < hist < HW, exact unless
    //   n is the later partner nB of a same-class pair -> sequential fixup.
    //   assign(nA) iff keep[nA]; assign(nB) iff keep[nB] && !keep[nA]
    if (t < NINST) { sci[t] = cls_idx[sord[t]]; hist[t] = 0; }
    if (t < 4) affected[t] = 0;
    __syncthreads();

    unsigned cnt = g_rawcnt; if (cnt > HW) cnt = HW;
    for (unsigned i = t; i < cnt; i += TPB) {
        unsigned long long r = g_rec[i];
        int nA = (int)(r >> 20) & 0x7F;
        int nB = (int)(r >> 27) & 0x7F;
        atomicAdd(&hist[nA], 1);
        if (nB < NINST) {
            atomicAdd(&hist[nB], 1);
            if (sci[nA] == sci[nB]) {
                unsigned pos = atomicAdd(&g_npairs, 1u);
                g_pair[pos] = (unsigned)nA | ((unsigned)nB << 8);
                atomicOr(&affected[nB >> 5], 1u << (nB & 31));
            }
        }
    }
    __syncthreads();

    unsigned np = g_npairs; if (np > HW) np = HW;
    if (t < NINST) skeep[t] = (hist[t] > 0 && hist[t] < HW) ? 1 : 0;
    __syncthreads();

    if (t < 32 && (affected[0] | affected[1] | affected[2] | affected[3])) {
        for (int n = 0; n < NINST; n++) {
            if (!((affected[n >> 5] >> (n & 31)) & 1u)) continue;
            if (!skeep[n]) continue;
            int ov = 0;
            for (unsigned i = t; i < np; i += 32) {
                unsigned pr = g_pair[i];
                if ((int)(pr >> 8) == n) ov += skeep[pr & 0xFFu];
            }
            ov = (int)__reduce_add_sync(0xffffffffu, (unsigned)ov);
            if (t == 0 && ((float)ov / fmaxf((float)hist[n], 1.0f)) > 0.03f)
                skeep[n] = 0;
            __syncwarp();
        }
    }
    __syncthreads();

    if (t < NINST && keep_out) keep_out[t] = skeep[t] ? 1.0f : 0.0f;

    for (unsigned i = t; i < cnt; i += TPB) {
        unsigned long long r = g_rec[i];
        unsigned p = (unsigned)(r & 0xFFFFFu);
        int nA = (int)(r >> 20) & 0x7F;
        int nB = (int)(r >> 27) & 0x7F;
        if (skeep[nA])
            masks_out[(size_t)nA * HW + p] = mask[(size_t)sord[nA] * HW + p];
        if (nB < NINST && skeep[nB] && !skeep[nA])
            masks_out[(size_t)nB * HW + p] = mask[(size_t)sord[nB] * HW + p];
    }

    __syncthreads();
    if (t == 0) { g_rawcnt = 0; g_npairs = 0; g_done = 0; g_tile = 0; } // replay reset
}

// ---------------- launch: pure-write memset, then pure-read kernel ----------------
extern "C" void kernel_launch(void* const* d_in, const int* in_sizes, int n_in,
                              void* d_out, int out_size) {
    const float* cls_prob = (const float*)d_in[0];
    const float* mask     = (const float*)d_in[1];
    const int*   cls_idx  = (const int*)d_in[2];
    float* out = (float*)d_out;

    size_t nhw = (size_t)NINST * HW;
    float* keep_out  = out;
    float* masks_out = out + NINST;
    float* order_out = out + NINST + nhw;
    if ((size_t)out_size < nhw + 2 * NINST) {   // layout fallback: masks only
        keep_out = nullptr; order_out = nullptr; masks_out = out;
    }

    cudaFuncSetAttribute(k_read, cudaFuncAttributeMaxDynamicSharedMemorySize,
                         SMEM_DYN);

    cudaMemsetAsync(d_out, 0, (size_t)out_size * sizeof(float), 0);
    k_read<<<GRID, TPB, SMEM_DYN>>>(mask, masks_out, cls_prob, cls_idx,
                                    keep_out, order_out);
}

// round 17
// speedup vs baseline: 1.2724x; 1.1115x over previous
#include <cuda_runtime.h>

#define NINST 100
#define HW 819200              // 640*1280
#define TPB 256
#define PXT 4                  // pixels per thread (float4)
#define NTILES 1600            // 800 reader + 800 writer tiles (parity-interleaved)
#define GRID 740               // 148 SMs x 5 resident blocks = single persistent wave
#define WCHUNK (NINST * HW / 800)    // 102400 floats per writer tile
#define UCH 8                  // planes per software-pipeline chunk

// ---------------- static device state (no allocations) ----------------
__device__ unsigned g_tile;                            // work-stealing cursor
__device__ unsigned g_rawcnt;                          // epilogue resets these
__device__ unsigned g_npairs;
__device__ unsigned g_done;
__device__ __align__(16) unsigned long long g_rec[HW]; // packed (p | nA<<20 | nB<<27)
__device__ __align__(16) unsigned g_pair[HW];          // packed (nA | nB<<8)

// ---------------- single fused persistent kernel ----------------
// 740 persistent blocks steal tiles 0..1599. Odd tiles: pure STG.128 zero-fill
// of the output planes. Even tiles: pure-read streaming max + unshifted
// sum(exp) over the 100 planes in descending-confidence order (argsort
// recomputed per block) + rare candidate emission (softmax >= 0.4 admits at
// most the per-pixel top-2). Work-stealing removes wave quantization and
// finish skew; role separation keeps read/write streams decoupled. This mixed
// concurrent structure sustains ~5.4-5.6 TB/s aggregate — measured above both
// the pure-read ceiling (4.4-4.65 TB/s, R13/R14/R16) and any temporal split.
// Phase 2 (last-finishing block): greedy merge on the compact record list.
__global__ void __launch_bounds__(TPB, 5) k_fused(const float* __restrict__ mask,
                                                  float* __restrict__ masks_out,
                                                  const float* __restrict__ cls_prob,
                                                  const int*   __restrict__ cls_idx,
                                                  float* keep_out, float* order_out) {
    __shared__ float v[NINST];
    __shared__ int sord[NINST];
    __shared__ int sci[NINST];
    __shared__ int hist[NINST];
    __shared__ int skeep[NINST];
    __shared__ unsigned affected[4];
    __shared__ unsigned stile;
    __shared__ int slast;

    int t = threadIdx.x;

    // ---- block-local argsort: stable ascending rank, reversed ----
    if (t < NINST) v[t] = cls_prob[t];
    __syncthreads();
    if (t < NINST) {
        float x = v[t];
        int r = 0;
#pragma unroll 4
        for (int j = 0; j < NINST; j++)
            r += (v[j] < x) || (v[j] == x && j < t);
        sord[NINST - 1 - r] = t;
    }
    __syncthreads();
    if (blockIdx.x == 0 && t < NINST && order_out) order_out[t] = (float)sord[t];

    // ---- persistent work-stealing loop over tiles ----
    for (;;) {
        if (t == 0) stile = atomicAdd(&g_tile, 1u);
        __syncthreads();
        unsigned tile = stile;
        __syncthreads();                       // stile reusable next iter
        if (tile >= NTILES) break;

        if (tile & 1u) {
            // ============== writer tile: pure zero-fill stream ==============
            const float4 z4 = make_float4(0.f, 0.f, 0.f, 0.f);
            float4* dst = reinterpret_cast<float4*>(
                masks_out + (size_t)(tile >> 1) * WCHUNK) + t;
#pragma unroll 4
            for (int i = 0; i < WCHUNK / (TPB * 4); i++) {
                __stcs(dst, z4);
                dst += TPB;
            }
        } else {
            // ============== reader tile: pure-read streaming reduce =========
            int p0 = (int)(tile >> 1) * (TPB * PXT) + t * PXT;

            float m1[PXT], s[PXT];
#pragma unroll
            for (int e = 0; e < PXT; e++) { m1[e] = __int_as_float(0xff800000); s[e] = 0.f; }

            float4 buf[UCH];
            for (int n0 = 0; n0 < 96; n0 += UCH) {
#pragma unroll
                for (int u = 0; u < UCH; u++)
                    buf[u] = __ldcs(reinterpret_cast<const float4*>(
                        mask + (size_t)sord[n0 + u] * HW + p0));
#pragma unroll
                for (int u = 0; u < UCH; u++) {
                    float vv[PXT] = { buf[u].x, buf[u].y, buf[u].z, buf[u].w };
#pragma unroll
                    for (int e = 0; e < PXT; e++) {
                        m1[e] = fmaxf(m1[e], vv[e]);
                        s[e] += __expf(vv[e]);
                    }
                }
            }
#pragma unroll
            for (int u = 0; u < 4; u++)
                buf[u] = __ldcs(reinterpret_cast<const float4*>(
                    mask + (size_t)sord[96 + u] * HW + p0));
#pragma unroll
            for (int u = 0; u < 4; u++) {
                float vv[PXT] = { buf[u].x, buf[u].y, buf[u].z, buf[u].w };
#pragma unroll
                for (int e = 0; e < PXT; e++) {
                    m1[e] = fmaxf(m1[e], vv[e]);
                    s[e] += __expf(vv[e]);
                }
            }

            // ---- rare candidate emission (second pass recovers top-2) ----
#pragma unroll
            for (int e = 0; e < PXT; e++) {
                float thr = 0.4f * s[e];
                if (__expf(m1[e]) >= thr) {
                    const float* col = mask + p0 + e;
                    float b1 = __int_as_float(0xff800000), b2 = b1;
                    int j1 = 127, j2 = 127;
                    for (int n = 0; n < NINST; n++) {
                        float val = __ldg(col + (size_t)sord[n] * HW);
                        bool g1 = val > b1;
                        bool g2 = val > b2;
                        j2 = g1 ? j1 : (g2 ? n : j2);
                        b2 = g1 ? b1 : (g2 ? val : b2);
                        j1 = g1 ? n : j1;
                        b1 = g1 ? val : b1;
                    }
                    bool c2 = (j2 < NINST) && (__expf(b2) >= thr);
                    int a = j1, b = c2 ? j2 : 127;
                    if (c2 && b < a) { int tmp = a; a = b; b = tmp; } // nA earlier
                    unsigned pos = atomicAdd(&g_rawcnt, 1u);
                    g_rec[pos] = (unsigned long long)(unsigned)(p0 + e)
                               | ((unsigned long long)a << 20)
                               | ((unsigned long long)b << 27);
                }
            }
        }
    }

    // ---- last-block-done handoff ----
    __syncthreads();
    __threadfence();                       // publish g_rec / output zeros
    if (t == 0) {
        unsigned old = atomicAdd(&g_done, 1u);
        slast = (old == (unsigned)(gridDim.x - 1)) ? 1 : 0;
    }
    __syncthreads();
    if (!slast) return;
    __threadfence();                       // acquire other blocks' records

    // ---- phase 2: greedy merge (one block) ----
    // overlap(n) > 0 requires a same-class pair at the same pixel (doubly rare):
    //   hist[n] = binarized mask_sum; default keep = 0 < hist < HW, exact unless
    //   n is the later partner nB of a same-class pair -> sequential fixup.
    //   assign(nA) iff keep[nA]; assign(nB) iff keep[nB] && !keep[nA]
    if (t < NINST) { sci[t] = cls_idx[sord[t]]; hist[t] = 0; }
    if (t < 4) affected[t] = 0;
    __syncthreads();

    unsigned cnt = g_rawcnt; if (cnt > HW) cnt = HW;
    for (unsigned i = t; i < cnt; i += TPB) {
        unsigned long long r = g_rec[i];
        int nA = (int)(r >> 20) & 0x7F;
        int nB = (int)(r >> 27) & 0x7F;
        atomicAdd(&hist[nA], 1);
        if (nB < NINST) {
            atomicAdd(&hist[nB], 1);
            if (sci[nA] == sci[nB]) {
                unsigned pos = atomicAdd(&g_npairs, 1u);
                g_pair[pos] = (unsigned)nA | ((unsigned)nB << 8);
                atomicOr(&affected[nB >> 5], 1u << (nB & 31));
            }
        }
    }
    __syncthreads();

    unsigned np = g_npairs; if (np > HW) np = HW;
    if (t < NINST) skeep[t] = (hist[t] > 0 && hist[t] < HW) ? 1 : 0;
    __syncthreads();

    if (t < 32 && (affected[0] | affected[1] | affected[2] | affected[3])) {
        for (int n = 0; n < NINST; n++) {
            if (!((affected[n >> 5] >> (n & 31)) & 1u)) continue;
            if (!skeep[n]) continue;
            int ov = 0;
            for (unsigned i = t; i < np; i += 32) {
                unsigned pr = g_pair[i];
                if ((int)(pr >> 8) == n) ov += skeep[pr & 0xFFu];
            }
            ov = (int)__reduce_add_sync(0xffffffffu, (unsigned)ov);
            if (t == 0 && ((float)ov / fmaxf((float)hist[n], 1.0f)) > 0.03f)
                skeep[n] = 0;
            __syncwarp();
        }
    }
    __syncthreads();

    if (t < NINST && keep_out) keep_out[t] = skeep[t] ? 1.0f : 0.0f;

    for (unsigned i = t; i < cnt; i += TPB) {
        unsigned long long r = g_rec[i];
        unsigned p = (unsigned)(r & 0xFFFFFu);
        int nA = (int)(r >> 20) & 0x7F;
        int nB = (int)(r >> 27) & 0x7F;
        if (skeep[nA])
            masks_out[(size_t)nA * HW + p] = mask[(size_t)sord[nA] * HW + p];
        if (nB < NINST && skeep[nB] && !skeep[nA])
            masks_out[(size_t)nB * HW + p] = mask[(size_t)sord[nB] * HW + p];
    }

    __syncthreads();
    if (t == 0) { g_rawcnt = 0; g_npairs = 0; g_done = 0; g_tile = 0; } // replay reset
}

// ---------------- launch (single persistent kernel) ----------------
extern "C" void kernel_launch(void* const* d_in, const int* in_sizes, int n_in,
                              void* d_out, int out_size) {
    const float* cls_prob = (const float*)d_in[0];
    const float* mask     = (const float*)d_in[1];
    const int*   cls_idx  = (const int*)d_in[2];
    float* out = (float*)d_out;

    size_t nhw = (size_t)NINST * HW;
    float* keep_out  = out;
    float* masks_out = out + NINST;
    float* order_out = out + NINST + nhw;
    if ((size_t)out_size < nhw + 2 * NINST) {   // layout fallback: masks only
        keep_out = nullptr; order_out = nullptr; masks_out = out;
    }

    k_fused<<<GRID, TPB>>>(mask, masks_out, cls_prob, cls_idx,
                           keep_out, order_out);
}